// round 8
// baseline (speedup 1.0000x reference)
#include <cuda_runtime.h>
#include <cuda_fp16.h>
#include <math.h>
#include <stdint.h>

// Problem sizes (fixed)
#define B_    16
#define S_    4096
#define D2_   1024      // 2H
#define H_    512
#define M_    (B_ * S_)

// Scratch
__device__ float g_hproj[B_ * H_];
__device__ float g_partial[8 * M_];          // per-ntile partial row sums (8 ntiles)
__device__ float g_scores[M_];               // softmaxed attention
__device__ float g_ctx[8 * B_ * D2_];        // per-schunk context partials
__device__ __half g_W16[D2_ * H_];           // W bottom, fp16, [k][n] row-major

// smem pitches (halves)
#define PA 40     // A rows: 32 halves + 8 pad
#define PB 72     // B rows: 64 halves + 8 pad (144 B, 16B-aligned)

// ---------------------------------------------------------------------------
// helpers
// ---------------------------------------------------------------------------
__device__ __forceinline__ uint32_t smem_u32(const void* p) {
    uint32_t a;
    asm("{ .reg .u64 t; cvta.to.shared.u64 t, %1; cvt.u32.u64 %0, t; }" : "=r"(a) : "l"(p));
    return a;
}
__device__ __forceinline__ void ldmx4(uint32_t addr, uint32_t& r0, uint32_t& r1,
                                      uint32_t& r2, uint32_t& r3) {
    asm volatile("ldmatrix.sync.aligned.m8n8.x4.shared.b16 {%0,%1,%2,%3}, [%4];"
                 : "=r"(r0), "=r"(r1), "=r"(r2), "=r"(r3) : "r"(addr));
}
__device__ __forceinline__ void ldmx4t(uint32_t addr, uint32_t& r0, uint32_t& r1,
                                       uint32_t& r2, uint32_t& r3) {
    asm volatile("ldmatrix.sync.aligned.m8n8.x4.trans.shared.b16 {%0,%1,%2,%3}, [%4];"
                 : "=r"(r0), "=r"(r1), "=r"(r2), "=r"(r3) : "r"(addr));
}
__device__ __forceinline__ void mma16816(float* c, uint32_t a0, uint32_t a1,
                                         uint32_t a2, uint32_t a3,
                                         uint32_t b0, uint32_t b1) {
    asm volatile(
        "mma.sync.aligned.m16n8k16.row.col.f32.f16.f16.f32 "
        "{%0,%1,%2,%3},{%4,%5,%6,%7},{%8,%9},{%0,%1,%2,%3};"
        : "+f"(c[0]), "+f"(c[1]), "+f"(c[2]), "+f"(c[3])
        : "r"(a0), "r"(a1), "r"(a2), "r"(a3), "r"(b0), "r"(b1));
}
__device__ __forceinline__ void cp16(uint32_t dst, const void* src) {
    asm volatile("cp.async.cg.shared.global [%0], [%1], 16;" :: "r"(dst), "l"(src));
}

// ---------------------------------------------------------------------------
// hproj[b][h] = b_attn[h] + hidden[b] @ W_top[:,h]   (fp32, tiny)
// ---------------------------------------------------------------------------
__global__ __launch_bounds__(512) void hproj_kernel(
    const float* __restrict__ hidden, const float* __restrict__ W,
    const float* __restrict__ b_attn)
{
    __shared__ float hid_s[D2_];
    int b = blockIdx.x, h = threadIdx.x;
    for (int d = threadIdx.x; d < D2_; d += blockDim.x)
        hid_s[d] = hidden[b * D2_ + d];
    __syncthreads();
    float acc = b_attn[h];
    #pragma unroll 8
    for (int d = 0; d < D2_; ++d)
        acc = fmaf(hid_s[d], W[(size_t)d * H_ + h], acc);
    g_hproj[b * H_ + h] = acc;
}

// ---------------------------------------------------------------------------
// pack W bottom [1024,512] fp32 -> fp16 [k][n]
// ---------------------------------------------------------------------------
__global__ __launch_bounds__(256) void wpack_kernel(const float* __restrict__ W) {
    int idx = blockIdx.x * 256 + threadIdx.x;
    g_W16[idx] = __float2half(W[(size_t)D2_ * H_ + idx]);
}

// ---------------------------------------------------------------------------
// scores GEMM: C = enc_f16 @ Wb_f16, CTA tile 128x64x32, 3 CTAs/SM.
// 8 warps: 4 m-groups (32 rows) x 2 n-groups (32 cols).
// ---------------------------------------------------------------------------
__global__ __launch_bounds__(256, 3) void scores_kernel(
    const float* __restrict__ enc, const float* __restrict__ wv)
{
    __shared__ __half As[2][128 * PA];     // 2 x 10 KB
    __shared__ __half Bs[2][32 * PB];      // 2 x 4.5 KB
    __shared__ float  hp_s[64], wv_s[64], red[256];

    const int tid = threadIdx.x, wid = tid >> 5, lane = tid & 31;
    const int mtile = blockIdx.x >> 3;     // ntile-fastest for L2 A reuse
    const int ntile = blockIdx.x & 7;
    const int b = mtile >> 5;

    if (tid < 64) {
        hp_s[tid] = g_hproj[b * H_ + ntile * 64 + tid];
        wv_s[tid] = wv[ntile * 64 + tid];
    }

    const float* Abase = enc + (size_t)mtile * 128 * D2_;
    const __half* Bbase = g_W16 + ntile * 64;

    // A: 2 threads/row, 4 float4 each (split into 2 halves of 2)
    const int ar  = tid >> 1;
    const int af0 = (tid & 1) * 4;
    // B cp.async: 256 16B-chunks, 1 per thread
    const int b_row = tid >> 3;            // 0..31
    const int b_c   = tid & 7;             // 0..7

    const uint32_t Bs_u32 = smem_u32(Bs);
    const uint32_t As_u32 = smem_u32(As);

    float4 av2[2];
    auto load_A_half = [&](int kc, int h) {
        const float* Ap = Abase + (size_t)ar * D2_ + kc * 32 + (af0 + h * 2) * 4;
        av2[0] = *(const float4*)(Ap);
        av2[1] = *(const float4*)(Ap + 4);
    };
    auto store_A_half = [&](int buf, int h) {
        __half2* dst = (__half2*)&As[buf][ar * PA + (af0 + h * 2) * 4];
        dst[0] = __floats2half2_rn(av2[0].x, av2[0].y);
        dst[1] = __floats2half2_rn(av2[0].z, av2[0].w);
        dst[2] = __floats2half2_rn(av2[1].x, av2[1].y);
        dst[3] = __floats2half2_rn(av2[1].z, av2[1].w);
    };
    auto issue_B = [&](int kc, int buf) {
        const __half* src = Bbase + (size_t)(kc * 32 + b_row) * H_ + b_c * 8;
        uint32_t dst = Bs_u32 + (uint32_t)(buf * 32 * PB + b_row * PB + b_c * 8) * 2;
        cp16(dst, src);
        asm volatile("cp.async.commit_group;" ::: "memory");
    };

    // accumulators: 2 m-atoms x 4 n-atoms x 4 f32 = 32 regs
    float acc[2][4][4];
    #pragma unroll
    for (int i = 0; i < 2; ++i)
        #pragma unroll
        for (int j = 0; j < 4; ++j)
            #pragma unroll
            for (int t = 0; t < 4; ++t) acc[i][j][t] = 0.0f;

    const int m_base = (wid >> 1) * 32;
    const int n_base = (wid & 1) * 32;
    const uint32_t a_off = ((m_base + (lane & 15)) * PA + (lane >> 4) * 8) * 2;
    const uint32_t b_off = (((lane & 7) + ((lane >> 3) & 1) * 8) * PB
                            + n_base + (lane >> 4) * 8) * 2;

    // prologue: chunk 0 into buffer 0
    issue_B(0, 0);
    load_A_half(0, 0); store_A_half(0, 0);
    load_A_half(0, 1); store_A_half(0, 1);
    asm volatile("cp.async.wait_group 0;" ::: "memory");
    __syncthreads();

    for (int kc = 0; kc < 32; ++kc) {
        const int buf = kc & 1;
        const bool more = (kc + 1 < 32);
        if (more) {
            issue_B(kc + 1, buf ^ 1);
            load_A_half(kc + 1, 0);
        }
        const uint32_t a_base = As_u32 + (uint32_t)buf * 128 * PA * 2 + a_off;
        const uint32_t b_base = Bs_u32 + (uint32_t)buf * 32 * PB * 2 + b_off;

        // ks = 0
        {
            uint32_t Af[2][4], Bf[2][4];
            #pragma unroll
            for (int ma = 0; ma < 2; ++ma)
                ldmx4(a_base + (ma * 16 * PA) * 2,
                      Af[ma][0], Af[ma][1], Af[ma][2], Af[ma][3]);
            #pragma unroll
            for (int g = 0; g < 2; ++g)
                ldmx4t(b_base + (g * 16) * 2,
                       Bf[g][0], Bf[g][1], Bf[g][2], Bf[g][3]);
            #pragma unroll
            for (int ma = 0; ma < 2; ++ma)
                #pragma unroll
                for (int j = 0; j < 4; ++j)
                    mma16816(acc[ma][j], Af[ma][0], Af[ma][1], Af[ma][2], Af[ma][3],
                             Bf[j >> 1][(j & 1) * 2], Bf[j >> 1][(j & 1) * 2 + 1]);
        }
        if (more) {
            store_A_half(buf ^ 1, 0);
            load_A_half(kc + 1, 1);
        }
        // ks = 1
        {
            uint32_t Af[2][4], Bf[2][4];
            #pragma unroll
            for (int ma = 0; ma < 2; ++ma)
                ldmx4(a_base + (ma * 16 * PA + 16) * 2,
                      Af[ma][0], Af[ma][1], Af[ma][2], Af[ma][3]);
            #pragma unroll
            for (int g = 0; g < 2; ++g)
                ldmx4t(b_base + (16 * PB + g * 16) * 2,
                       Bf[g][0], Bf[g][1], Bf[g][2], Bf[g][3]);
            #pragma unroll
            for (int ma = 0; ma < 2; ++ma)
                #pragma unroll
                for (int j = 0; j < 4; ++j)
                    mma16816(acc[ma][j], Af[ma][0], Af[ma][1], Af[ma][2], Af[ma][3],
                             Bf[j >> 1][(j & 1) * 2], Bf[j >> 1][(j & 1) * 2 + 1]);
        }
        if (more) {
            store_A_half(buf ^ 1, 1);
            asm volatile("cp.async.wait_group 0;" ::: "memory");
        }
        __syncthreads();
    }

    // ---- epilogue (validated mapping, n-range halved) ----
    #pragma unroll
    for (int ma = 0; ma < 2; ++ma) {
        float rs0 = 0.0f, rs1 = 0.0f;
        #pragma unroll
        for (int j = 0; j < 4; ++j) {
            int col = n_base + j * 8 + (lane & 3) * 2;
            float h0 = hp_s[col], h1 = hp_s[col + 1];
            float w0 = wv_s[col], w1 = wv_s[col + 1];
            rs0 = fmaf(tanhf(acc[ma][j][0] + h0), w0, rs0);
            rs0 = fmaf(tanhf(acc[ma][j][1] + h1), w1, rs0);
            rs1 = fmaf(tanhf(acc[ma][j][2] + h0), w0, rs1);
            rs1 = fmaf(tanhf(acc[ma][j][3] + h1), w1, rs1);
        }
        #pragma unroll
        for (int off = 1; off <= 2; off <<= 1) {
            rs0 += __shfl_xor_sync(0xffffffffu, rs0, off);
            rs1 += __shfl_xor_sync(0xffffffffu, rs1, off);
        }
        if ((lane & 3) == 0) {
            int r0 = m_base + ma * 16 + (lane >> 2);
            red[r0 * 2 + (wid & 1)] = rs0;
            red[(r0 + 8) * 2 + (wid & 1)] = rs1;
        }
    }
    __syncthreads();
    if (tid < 128)
        g_partial[(size_t)ntile * M_ + mtile * 128 + tid] = red[tid * 2] + red[tid * 2 + 1];
}

// ---------------------------------------------------------------------------
// softmax: fold 8 n-tile partials, softmax over S, write g_scores. grid=B_.
// ---------------------------------------------------------------------------
__global__ __launch_bounds__(512) void softmax_kernel() {
    __shared__ float sc_s[S_];
    __shared__ float red2[512];
    const int b = blockIdx.x, tid = threadIdx.x;

    float lmax = -1e30f;
    for (int s = tid; s < S_; s += 512) {
        size_t m = (size_t)b * S_ + s;
        float v = 0.0f;
        #pragma unroll
        for (int p = 0; p < 8; ++p) v += g_partial[(size_t)p * M_ + m];
        sc_s[s] = v;
        lmax = fmaxf(lmax, v);
    }
    red2[tid] = lmax; __syncthreads();
    for (int off = 256; off >= 1; off >>= 1) {
        if (tid < off) red2[tid] = fmaxf(red2[tid], red2[tid + off]);
        __syncthreads();
    }
    const float mx = red2[0];
    __syncthreads();
    float lsum = 0.0f;
    for (int s = tid; s < S_; s += 512) {
        float e = __expf(sc_s[s] - mx);
        sc_s[s] = e;
        lsum += e;
    }
    red2[tid] = lsum; __syncthreads();
    for (int off = 256; off >= 1; off >>= 1) {
        if (tid < off) red2[tid] += red2[tid + off];
        __syncthreads();
    }
    const float inv = 1.0f / red2[0];
    __syncthreads();
    for (int s = tid; s < S_; s += 512)
        g_scores[b * S_ + s] = sc_s[s] * inv;
}

// ---------------------------------------------------------------------------
// context partials: grid (B_, 8 dcols, 8 schunks), 256 threads.
// ---------------------------------------------------------------------------
__global__ __launch_bounds__(256) void context_kernel(const float* __restrict__ enc)
{
    __shared__ float attn_s[512];
    __shared__ float redc[8][128];

    const int b = blockIdx.x, dc = blockIdx.y, sc = blockIdx.z, tid = threadIdx.x;
    const int s0 = sc * 512;

    for (int s = tid; s < 512; s += 256)
        attn_s[s] = g_scores[b * S_ + s0 + s];
    __syncthreads();

    const int tsub = tid >> 5, lane = tid & 31;
    const float* base = enc + (size_t)b * S_ * D2_ + (size_t)s0 * D2_
                        + dc * 128 + lane * 4;
    float4 acc = make_float4(0.f, 0.f, 0.f, 0.f);
    #pragma unroll 8
    for (int s = tsub; s < 512; s += 8) {
        float a  = attn_s[s];
        float4 e = *(const float4*)(base + (size_t)s * D2_);
        acc.x = fmaf(a, e.x, acc.x);
        acc.y = fmaf(a, e.y, acc.y);
        acc.z = fmaf(a, e.z, acc.z);
        acc.w = fmaf(a, e.w, acc.w);
    }
    *(float4*)&redc[tsub][lane * 4] = acc;
    __syncthreads();
    if (tid < 128) {
        float s = 0.0f;
        #pragma unroll
        for (int t = 0; t < 8; ++t) s += redc[t][tid];
        g_ctx[((size_t)sc * B_ + b) * D2_ + dc * 128 + tid] = s;
    }
}

// ---------------------------------------------------------------------------
// reduce 8 context partials -> out
// ---------------------------------------------------------------------------
__global__ __launch_bounds__(256) void ctx_reduce_kernel(float* __restrict__ out) {
    int i = blockIdx.x * 256 + threadIdx.x;
    float s = 0.0f;
    #pragma unroll
    for (int p = 0; p < 8; ++p) s += g_ctx[(size_t)p * B_ * D2_ + i];
    out[i] = s;
}

// ---------------------------------------------------------------------------
// Launch
// ---------------------------------------------------------------------------
extern "C" void kernel_launch(void* const* d_in, const int* in_sizes, int n_in,
                              void* d_out, int out_size) {
    const float* hidden = (const float*)d_in[0];
    const float* enc    = (const float*)d_in[1];
    const float* W      = (const float*)d_in[2];
    const float* b_attn = (const float*)d_in[3];
    const float* wv     = (const float*)d_in[4];
    float* out = (float*)d_out;

    hproj_kernel<<<B_, 512>>>(hidden, W, b_attn);
    wpack_kernel<<<(D2_ * H_) / 256, 256>>>(W);
    scores_kernel<<<(M_ / 128) * 8, 256>>>(enc, wv);
    softmax_kernel<<<B_, 512>>>();
    context_kernel<<<dim3(B_, 8, 8), 256>>>(enc);
    ctx_reduce_kernel<<<(B_ * D2_) / 256, 256>>>(out);
}

// round 9
// speedup vs baseline: 1.4676x; 1.4676x over previous
#include <cuda_runtime.h>
#include <cuda_fp16.h>
#include <math.h>
#include <stdint.h>

// Problem sizes (fixed)
#define B_    16
#define S_    4096
#define D2_   1024      // 2H
#define H_    512
#define M_    (B_ * S_)

// Scratch
__device__ float g_hproj[B_ * H_];
__device__ float g_partial[4 * M_];          // per-ntile partial row sums
__device__ float g_scores[M_];               // softmaxed attention
__device__ float g_ctx[8 * B_ * D2_];        // per-schunk context partials
__device__ __half g_W16[D2_ * H_];           // W bottom fp16 [k][n]
__device__ uint4  g_enc16[(size_t)M_ * D2_ / 8];   // enc fp16, row-major [M][1024]

// smem pitches (halves)
#define PA 40     // A rows: 32 halves + 8 pad (80 B)
#define PB 136    // B rows: 128 halves + 8 pad (272 B)
#define STAGES 4
#define ASZ (128 * PA)          // 5120 halves
#define BSZ (32 * PB)           // 4352 halves
#define STAGE_BYTES ((ASZ + BSZ) * 2)        // 18944
#define SMEM_DYN (STAGES * STAGE_BYTES)      // 75776

// ---------------------------------------------------------------------------
// helpers
// ---------------------------------------------------------------------------
__device__ __forceinline__ uint32_t smem_u32(const void* p) {
    uint32_t a;
    asm("{ .reg .u64 t; cvta.to.shared.u64 t, %1; cvt.u32.u64 %0, t; }" : "=r"(a) : "l"(p));
    return a;
}
__device__ __forceinline__ void ldmx4(uint32_t addr, uint32_t& r0, uint32_t& r1,
                                      uint32_t& r2, uint32_t& r3) {
    asm volatile("ldmatrix.sync.aligned.m8n8.x4.shared.b16 {%0,%1,%2,%3}, [%4];"
                 : "=r"(r0), "=r"(r1), "=r"(r2), "=r"(r3) : "r"(addr));
}
__device__ __forceinline__ void ldmx4t(uint32_t addr, uint32_t& r0, uint32_t& r1,
                                       uint32_t& r2, uint32_t& r3) {
    asm volatile("ldmatrix.sync.aligned.m8n8.x4.trans.shared.b16 {%0,%1,%2,%3}, [%4];"
                 : "=r"(r0), "=r"(r1), "=r"(r2), "=r"(r3) : "r"(addr));
}
__device__ __forceinline__ void mma16816(float* c, uint32_t a0, uint32_t a1,
                                         uint32_t a2, uint32_t a3,
                                         uint32_t b0, uint32_t b1) {
    asm volatile(
        "mma.sync.aligned.m16n8k16.row.col.f32.f16.f16.f32 "
        "{%0,%1,%2,%3},{%4,%5,%6,%7},{%8,%9},{%0,%1,%2,%3};"
        : "+f"(c[0]), "+f"(c[1]), "+f"(c[2]), "+f"(c[3])
        : "r"(a0), "r"(a1), "r"(a2), "r"(a3), "r"(b0), "r"(b1));
}
__device__ __forceinline__ void cp16(uint32_t dst, const void* src) {
    asm volatile("cp.async.cg.shared.global [%0], [%1], 16;" :: "r"(dst), "l"(src));
}

// ---------------------------------------------------------------------------
// hproj[b][h] = b_attn[h] + hidden[b] @ W_top[:,h]
// ---------------------------------------------------------------------------
__global__ __launch_bounds__(512) void hproj_kernel(
    const float* __restrict__ hidden, const float* __restrict__ W,
    const float* __restrict__ b_attn)
{
    __shared__ float hid_s[D2_];
    int b = blockIdx.x, h = threadIdx.x;
    for (int d = threadIdx.x; d < D2_; d += blockDim.x)
        hid_s[d] = hidden[b * D2_ + d];
    __syncthreads();
    float acc = b_attn[h];
    #pragma unroll 8
    for (int d = 0; d < D2_; ++d)
        acc = fmaf(hid_s[d], W[(size_t)d * H_ + h], acc);
    g_hproj[b * H_ + h] = acc;
}

// ---------------------------------------------------------------------------
// pack W bottom [1024,512] fp32 -> fp16 [k][n]
// ---------------------------------------------------------------------------
__global__ __launch_bounds__(256) void wpack_kernel(const float* __restrict__ W) {
    int idx = blockIdx.x * 256 + threadIdx.x;
    g_W16[idx] = __float2half(W[(size_t)D2_ * H_ + idx]);
}

// ---------------------------------------------------------------------------
// pack enc [M,1024] fp32 -> fp16 (8 elems / thread)
// ---------------------------------------------------------------------------
__global__ __launch_bounds__(256) void epack_kernel(const float* __restrict__ enc) {
    size_t idx = (size_t)blockIdx.x * 256 + threadIdx.x;   // 0 .. 8M-1
    const float4* src = (const float4*)enc + idx * 2;
    float4 f0 = src[0], f1 = src[1];
    __half2 h0 = __floats2half2_rn(f0.x, f0.y);
    __half2 h1 = __floats2half2_rn(f0.z, f0.w);
    __half2 h2 = __floats2half2_rn(f1.x, f1.y);
    __half2 h3 = __floats2half2_rn(f1.z, f1.w);
    uint4 o;
    o.x = *(uint32_t*)&h0; o.y = *(uint32_t*)&h1;
    o.z = *(uint32_t*)&h2; o.w = *(uint32_t*)&h3;
    g_enc16[idx] = o;
}

// ---------------------------------------------------------------------------
// scores GEMM: C = enc16 @ W16, CTA 128x128x32, 4-stage cp.async pipeline,
// 2 CTAs/SM. Hot loop = LDSM + HMMA only.
// ---------------------------------------------------------------------------
__global__ __launch_bounds__(256, 2) void scores_kernel(const float* __restrict__ wv)
{
    extern __shared__ __align__(16) char dsm[];
    __shared__ float hp_s[128], wv_s[128], red[256];

    const int tid = threadIdx.x, wid = tid >> 5, lane = tid & 31;
    const int mtile = blockIdx.x >> 2;     // ntile-fastest for L2 A reuse
    const int ntile = blockIdx.x & 3;
    const int b = mtile >> 5;

    if (tid < 128) {
        hp_s[tid] = g_hproj[b * H_ + ntile * 128 + tid];
        wv_s[tid] = wv[ntile * 128 + tid];
    }

    const __half* Aenc = (const __half*)g_enc16 + (size_t)mtile * 128 * D2_;
    const __half* Bw   = g_W16 + ntile * 128;
    const uint32_t sm_b = smem_u32(dsm);

    const int ac0 = tid * 2;
    auto issue_stage = [&](int kc, int s) {
        uint32_t base = sm_b + (uint32_t)s * STAGE_BYTES;
        #pragma unroll
        for (int i = 0; i < 2; ++i) {
            int c = ac0 + i;
            int row = c >> 2, cc = c & 3;
            cp16(base + (uint32_t)(row * PA * 2 + cc * 16),
                 Aenc + (size_t)row * D2_ + kc * 32 + cc * 8);
        }
        uint32_t bbase = base + ASZ * 2;
        #pragma unroll
        for (int i = 0; i < 2; ++i) {
            int c = ac0 + i;
            int row = c >> 4, cc = c & 15;
            cp16(bbase + (uint32_t)(row * PB * 2 + cc * 16),
                 Bw + (size_t)(kc * 32 + row) * H_ + cc * 8);
        }
        asm volatile("cp.async.commit_group;" ::: "memory");
    };

    float acc[2][8][4];
    #pragma unroll
    for (int i = 0; i < 2; ++i)
        #pragma unroll
        for (int j = 0; j < 8; ++j)
            #pragma unroll
            for (int t = 0; t < 4; ++t) acc[i][j][t] = 0.0f;

    const int m_base = (wid >> 1) * 32;
    const int n_base = (wid & 1) * 64;
    const uint32_t a_off = ((m_base + (lane & 15)) * PA + (lane >> 4) * 8) * 2;
    const uint32_t b_off = (((lane & 7) + ((lane >> 3) & 1) * 8) * PB
                            + n_base + (lane >> 4) * 8) * 2;

    issue_stage(0, 0);
    issue_stage(1, 1);
    issue_stage(2, 2);

    for (int kc = 0; kc < 32; ++kc) {
        asm volatile("cp.async.wait_group 2;" ::: "memory");
        __syncthreads();
        if (kc + 3 < 32) issue_stage(kc + 3, (kc + 3) & (STAGES - 1));

        const uint32_t sbase = sm_b + (uint32_t)(kc & (STAGES - 1)) * STAGE_BYTES;
        const uint32_t a_base = sbase + a_off;
        const uint32_t b_base = sbase + ASZ * 2 + b_off;
        #pragma unroll
        for (int ks = 0; ks < 2; ++ks) {
            uint32_t Af[2][4], Bf[4][4];
            #pragma unroll
            for (int ma = 0; ma < 2; ++ma)
                ldmx4(a_base + (ma * 16 * PA + ks * 16) * 2,
                      Af[ma][0], Af[ma][1], Af[ma][2], Af[ma][3]);
            #pragma unroll
            for (int g = 0; g < 4; ++g)
                ldmx4t(b_base + (ks * 16 * PB + g * 16) * 2,
                       Bf[g][0], Bf[g][1], Bf[g][2], Bf[g][3]);
            #pragma unroll
            for (int ma = 0; ma < 2; ++ma)
                #pragma unroll
                for (int j = 0; j < 8; ++j)
                    mma16816(acc[ma][j], Af[ma][0], Af[ma][1], Af[ma][2], Af[ma][3],
                             Bf[j >> 1][(j & 1) * 2], Bf[j >> 1][(j & 1) * 2 + 1]);
        }
        __syncthreads();
    }

    // ---- epilogue (validated mapping) ----
    #pragma unroll
    for (int ma = 0; ma < 2; ++ma) {
        float rs0 = 0.0f, rs1 = 0.0f;
        #pragma unroll
        for (int j = 0; j < 8; ++j) {
            int col = n_base + j * 8 + (lane & 3) * 2;
            float h0 = hp_s[col], h1 = hp_s[col + 1];
            float w0 = wv_s[col], w1 = wv_s[col + 1];
            rs0 = fmaf(tanhf(acc[ma][j][0] + h0), w0, rs0);
            rs0 = fmaf(tanhf(acc[ma][j][1] + h1), w1, rs0);
            rs1 = fmaf(tanhf(acc[ma][j][2] + h0), w0, rs1);
            rs1 = fmaf(tanhf(acc[ma][j][3] + h1), w1, rs1);
        }
        #pragma unroll
        for (int off = 1; off <= 2; off <<= 1) {
            rs0 += __shfl_xor_sync(0xffffffffu, rs0, off);
            rs1 += __shfl_xor_sync(0xffffffffu, rs1, off);
        }
        if ((lane & 3) == 0) {
            int r0 = m_base + ma * 16 + (lane >> 2);
            red[r0 * 2 + (wid & 1)] = rs0;
            red[(r0 + 8) * 2 + (wid & 1)] = rs1;
        }
    }
    __syncthreads();
    if (tid < 128)
        g_partial[(size_t)ntile * M_ + mtile * 128 + tid] = red[tid * 2] + red[tid * 2 + 1];
}

// ---------------------------------------------------------------------------
// softmax: fold 4 n-tile partials, softmax over S, write g_scores. grid=B_.
// ---------------------------------------------------------------------------
__global__ __launch_bounds__(512) void softmax_kernel() {
    __shared__ float sc_s[S_];
    __shared__ float red2[512];
    const int b = blockIdx.x, tid = threadIdx.x;

    float lmax = -1e30f;
    for (int s = tid; s < S_; s += 512) {
        size_t m = (size_t)b * S_ + s;
        float v = g_partial[m] + g_partial[M_ + m] +
                  g_partial[2 * (size_t)M_ + m] + g_partial[3 * (size_t)M_ + m];
        sc_s[s] = v;
        lmax = fmaxf(lmax, v);
    }
    red2[tid] = lmax; __syncthreads();
    for (int off = 256; off >= 1; off >>= 1) {
        if (tid < off) red2[tid] = fmaxf(red2[tid], red2[tid + off]);
        __syncthreads();
    }
    const float mx = red2[0];
    __syncthreads();
    float lsum = 0.0f;
    for (int s = tid; s < S_; s += 512) {
        float e = __expf(sc_s[s] - mx);
        sc_s[s] = e;
        lsum += e;
    }
    red2[tid] = lsum; __syncthreads();
    for (int off = 256; off >= 1; off >>= 1) {
        if (tid < off) red2[tid] += red2[tid + off];
        __syncthreads();
    }
    const float inv = 1.0f / red2[0];
    __syncthreads();
    for (int s = tid; s < S_; s += 512)
        g_scores[b * S_ + s] = sc_s[s] * inv;
}

// ---------------------------------------------------------------------------
// context partials from fp16 enc: grid (B_, 8 dcols, 8 schunks), 256 threads.
// ---------------------------------------------------------------------------
__global__ __launch_bounds__(256) void context_kernel()
{
    __shared__ float attn_s[512];
    __shared__ float redc[8][128];

    const int b = blockIdx.x, dc = blockIdx.y, sc = blockIdx.z, tid = threadIdx.x;
    const int s0 = sc * 512;

    for (int s = tid; s < 512; s += 256)
        attn_s[s] = g_scores[b * S_ + s0 + s];
    __syncthreads();

    const int tsub = tid >> 5, lane = tid & 31;
    const __half* base = (const __half*)g_enc16
                       + ((size_t)b * S_ + s0) * D2_ + dc * 128 + lane * 4;
    float4 acc = make_float4(0.f, 0.f, 0.f, 0.f);
    #pragma unroll 8
    for (int s = tsub; s < 512; s += 8) {
        float a = attn_s[s];
        uint2 raw = *(const uint2*)(base + (size_t)s * D2_);
        float2 e0 = __half22float2(*(__half2*)&raw.x);
        float2 e1 = __half22float2(*(__half2*)&raw.y);
        acc.x = fmaf(a, e0.x, acc.x);
        acc.y = fmaf(a, e0.y, acc.y);
        acc.z = fmaf(a, e1.x, acc.z);
        acc.w = fmaf(a, e1.y, acc.w);
    }
    *(float4*)&redc[tsub][lane * 4] = acc;
    __syncthreads();
    if (tid < 128) {
        float s = 0.0f;
        #pragma unroll
        for (int t = 0; t < 8; ++t) s += redc[t][tid];
        g_ctx[((size_t)sc * B_ + b) * D2_ + dc * 128 + tid] = s;
    }
}

// ---------------------------------------------------------------------------
// reduce 8 context partials -> out
// ---------------------------------------------------------------------------
__global__ __launch_bounds__(256) void ctx_reduce_kernel(float* __restrict__ out) {
    int i = blockIdx.x * 256 + threadIdx.x;
    float s = 0.0f;
    #pragma unroll
    for (int p = 0; p < 8; ++p) s += g_ctx[(size_t)p * B_ * D2_ + i];
    out[i] = s;
}

// ---------------------------------------------------------------------------
// Launch
// ---------------------------------------------------------------------------
extern "C" void kernel_launch(void* const* d_in, const int* in_sizes, int n_in,
                              void* d_out, int out_size) {
    const float* hidden = (const float*)d_in[0];
    const float* enc    = (const float*)d_in[1];
    const float* W      = (const float*)d_in[2];
    const float* b_attn = (const float*)d_in[3];
    const float* wv     = (const float*)d_in[4];
    float* out = (float*)d_out;

    static int smem_set = 0;
    if (!smem_set) {
        cudaFuncSetAttribute(scores_kernel,
                             cudaFuncAttributeMaxDynamicSharedMemorySize, SMEM_DYN);
        smem_set = 1;
    }

    hproj_kernel<<<B_, 512>>>(hidden, W, b_attn);
    wpack_kernel<<<(D2_ * H_) / 256, 256>>>(W);
    epack_kernel<<<(unsigned)(((size_t)M_ * D2_ / 8) / 256), 256>>>(enc);
    scores_kernel<<<(M_ / 128) * 4, 256, SMEM_DYN>>>(wv);
    softmax_kernel<<<B_, 512>>>();
    context_kernel<<<dim3(B_, 8, 8), 256>>>();
    ctx_reduce_kernel<<<(B_ * D2_) / 256, 256>>>(out);
}